// round 1
// baseline (speedup 1.0000x reference)
#include <cuda_runtime.h>

// ---------------------------------------------------------------------------
// MutationAwareGNN: 3-layer GCN + global mean pool + 2-layer MLP head.
// N=100000 nodes, E=3.2M edges, G=256 graphs. All scratch in __device__ globals.
// Strategy: build CSR by dst once per launch, pull-based aggregation (no float
// atomics), dinv folded into GEMM output so aggregation is a pure gather-sum.
// ---------------------------------------------------------------------------

#define NMAX 100000
#define EMAX 3200000
#define GMAX 256

__device__ int   g_deg[NMAX];
__device__ int   g_rowptr[NMAX + 1];
__device__ int   g_cursor[NMAX];
__device__ int   g_bsums[1024];
__device__ int   g_col[EMAX];
__device__ float g_dinv[NMAX];
__device__ float g_bufA[NMAX * 64];   // hs = dinv * (X @ W)
__device__ float g_bufB[NMAX * 64];   // layer output (post-ReLU)

// ---------------------------- CSR construction ----------------------------

__global__ void k_zero_deg(int n) {
    int i = blockIdx.x * blockDim.x + threadIdx.x;
    if (i < n) g_deg[i] = 0;
}

__global__ void k_count(const int* __restrict__ dst, int E) {
    int e = blockIdx.x * blockDim.x + threadIdx.x;
    if (e < E) atomicAdd(&g_deg[dst[e]], 1);
}

// Per-1024-chunk exclusive scan; chunk totals into g_bsums.
__global__ void k_scan1(int n) {
    __shared__ int s[1024];
    int i = blockIdx.x * 1024 + threadIdx.x;
    int v = (i < n) ? g_deg[i] : 0;
    s[threadIdx.x] = v;
    __syncthreads();
    for (int off = 1; off < 1024; off <<= 1) {
        int t = (threadIdx.x >= (unsigned)off) ? s[threadIdx.x - off] : 0;
        __syncthreads();
        s[threadIdx.x] += t;
        __syncthreads();
    }
    if (i < n) g_rowptr[i] = s[threadIdx.x] - v;  // exclusive within chunk
    if (threadIdx.x == 1023) g_bsums[blockIdx.x] = s[1023];
}

__global__ void k_scan2(int nb) {
    if (blockIdx.x == 0 && threadIdx.x == 0) {
        int acc = 0;
        for (int b = 0; b < nb; b++) { int t = g_bsums[b]; g_bsums[b] = acc; acc += t; }
    }
}

__global__ void k_scan3(int n, int E) {
    int i = blockIdx.x * blockDim.x + threadIdx.x;
    if (i < n) {
        int r = g_rowptr[i] + g_bsums[i >> 10];
        g_rowptr[i] = r;
        g_cursor[i] = r;
        g_dinv[i]   = rsqrtf((float)(g_deg[i] + 1));  // +1 self-loop
        if (i == 0) g_rowptr[n] = E;
    }
}

__global__ void k_fill(const int* __restrict__ src, const int* __restrict__ dst, int E) {
    int e = blockIdx.x * blockDim.x + threadIdx.x;
    if (e < E) {
        int d = dst[e];
        int p = atomicAdd(&g_cursor[d], 1);
        g_col[p] = src[e];
    }
}

// ------------------------------- Dense GEMM --------------------------------
// out = dinv[row] * (X @ W), X: [n, FIN], W: [FIN, FOUT] row-major.
// SRCSEL: 0 -> input from param pointer (layer 1: x), 1 -> input from g_bufB.
// Thread computes 4 consecutive output features (float4 acc, LDS.128 on W).

template <int FIN, int FOUT, int SRCSEL>
__global__ void k_gemm(const float* __restrict__ Xp, const float* __restrict__ W, int n) {
    __shared__ float Wsh[FIN * FOUT];
    for (int i = threadIdx.x; i < FIN * FOUT; i += blockDim.x) Wsh[i] = W[i];
    __syncthreads();

    const float* __restrict__ X = (SRCSEL == 0) ? Xp : g_bufB;
    constexpr int TPR = FOUT / 4;       // threads per row
    constexpr int RPB = 256 / TPR;      // rows per block
    int row = blockIdx.x * RPB + (int)(threadIdx.x / TPR);
    if (row >= n) return;
    int fx = (threadIdx.x % TPR) * 4;

    const float* xr = X + (long)row * FIN;
    float4 acc = make_float4(0.f, 0.f, 0.f, 0.f);
#pragma unroll
    for (int k = 0; k < FIN; k++) {
        float xv = __ldg(&xr[k]);
        float4 w = *reinterpret_cast<const float4*>(&Wsh[k * FOUT + fx]);
        acc.x = fmaf(xv, w.x, acc.x);
        acc.y = fmaf(xv, w.y, acc.y);
        acc.z = fmaf(xv, w.z, acc.z);
        acc.w = fmaf(xv, w.w, acc.w);
    }
    float d = g_dinv[row];
    acc.x *= d; acc.y *= d; acc.z *= d; acc.w *= d;
    *reinterpret_cast<float4*>(&g_bufA[(long)row * FOUT + fx]) = acc;
}

// ----------------------------- Aggregation ---------------------------------
// Warp per node: out_i = relu(dinv_i * (hs_i + sum_j hs_j) + bias)
// F=64: float2 per lane. F=32: float per lane. Reads g_bufA, writes g_bufB.

template <int F>
__global__ void k_agg(const float* __restrict__ bias, int n) {
    int gw   = (blockIdx.x * blockDim.x + threadIdx.x) >> 5;
    int lane = threadIdx.x & 31;
    if (gw >= n) return;
    int beg = g_rowptr[gw], end = g_rowptr[gw + 1];

    if (F == 64) {
        const float2* base = reinterpret_cast<const float2*>(g_bufA);
        float2 acc = base[gw * 32 + lane];  // self-loop term hs_i
        int e = beg;
        for (; e + 1 < end; e += 2) {
            int j0 = __ldg(&g_col[e]);
            int j1 = __ldg(&g_col[e + 1]);
            float2 v0 = base[j0 * 32 + lane];
            float2 v1 = base[j1 * 32 + lane];
            acc.x += v0.x + v1.x;
            acc.y += v0.y + v1.y;
        }
        if (e < end) {
            int j = __ldg(&g_col[e]);
            float2 v = base[j * 32 + lane];
            acc.x += v.x; acc.y += v.y;
        }
        float d = g_dinv[gw];
        float2 r;
        r.x = fmaxf(fmaf(acc.x, d, bias[lane * 2 + 0]), 0.f);
        r.y = fmaxf(fmaf(acc.y, d, bias[lane * 2 + 1]), 0.f);
        *reinterpret_cast<float2*>(&g_bufB[(long)gw * 64 + lane * 2]) = r;
    } else {  // F == 32
        float acc = g_bufA[(long)gw * 32 + lane];
        int e = beg;
        for (; e + 1 < end; e += 2) {
            int j0 = __ldg(&g_col[e]);
            int j1 = __ldg(&g_col[e + 1]);
            acc += g_bufA[(long)j0 * 32 + lane] + g_bufA[(long)j1 * 32 + lane];
        }
        if (e < end) acc += g_bufA[(long)__ldg(&g_col[e]) * 32 + lane];
        g_bufB[(long)gw * 32 + lane] =
            fmaxf(fmaf(acc, g_dinv[gw], bias[lane]), 0.f);
    }
}

// ------------------------- Pool + MLP head (fused) --------------------------
// batch is sorted: block g binary-searches its node range, mean-pools 32
// features, then warp 0 runs the 32->32->1 MLP and writes out[g].

__global__ void k_pool_mlp(const int* __restrict__ batch, int n,
                           const float* __restrict__ Wh1, const float* __restrict__ bh1,
                           const float* __restrict__ Wh2, const float* __restrict__ bh2,
                           float* __restrict__ out) {
    int g = blockIdx.x;
    // lower_bound(batch, g)
    int lo = 0, hi = n;
    while (lo < hi) { int mid = (lo + hi) >> 1; if (batch[mid] < g) lo = mid + 1; else hi = mid; }
    int start = lo;
    // lower_bound(batch, g+1)
    hi = n;
    while (lo < hi) { int mid = (lo + hi) >> 1; if (batch[mid] < g + 1) lo = mid + 1; else hi = mid; }
    int end = lo;

    __shared__ float partial[4][32];
    __shared__ float gsum[32];
    int f = threadIdx.x & 31;
    int r = threadIdx.x >> 5;  // 0..3 (blockDim = 128)
    float acc = 0.f;
    for (int i = start + r; i < end; i += 4) acc += g_bufB[(long)i * 32 + f];
    partial[r][f] = acc;
    __syncthreads();

    if (threadIdx.x < 32) {
        float s = partial[0][f] + partial[1][f] + partial[2][f] + partial[3][f];
        float cnt = (float)((end - start) > 0 ? (end - start) : 1);
        gsum[f] = s / cnt;
    }
    __syncthreads();

    if (threadIdx.x < 32) {
        int o = threadIdx.x;
        float h = bh1[o];
#pragma unroll
        for (int k = 0; k < 32; k++) h = fmaf(gsum[k], Wh1[k * 32 + o], h);
        h = fmaxf(h, 0.f);
        float y = h * Wh2[o];
#pragma unroll
        for (int off = 16; off; off >>= 1) y += __shfl_down_sync(0xffffffffu, y, off);
        if (o == 0) out[g] = y + bh2[0];
    }
}

// ------------------------------- Launcher ----------------------------------

extern "C" void kernel_launch(void* const* d_in, const int* in_sizes, int n_in,
                              void* d_out, int out_size) {
    const float* x     = (const float*)d_in[0];
    const int*   ei    = (const int*)d_in[1];
    const int*   batch = (const int*)d_in[2];
    const float* W1  = (const float*)d_in[3];
    const float* b1  = (const float*)d_in[4];
    const float* W2  = (const float*)d_in[5];
    const float* b2  = (const float*)d_in[6];
    const float* W3  = (const float*)d_in[7];
    const float* b3  = (const float*)d_in[8];
    const float* Wh1 = (const float*)d_in[9];
    const float* bh1 = (const float*)d_in[10];
    const float* Wh2 = (const float*)d_in[11];
    const float* bh2 = (const float*)d_in[12];
    float* out = (float*)d_out;

    int N = in_sizes[0] / 25;
    int E = in_sizes[1] / 2;
    const int* src = ei;
    const int* dst = ei + E;

    int nThreads = 256;
    int nBlkN = (N + nThreads - 1) / nThreads;
    int nBlkE = (E + nThreads - 1) / nThreads;
    int nbScan = (N + 1023) / 1024;

    // --- CSR build ---
    k_zero_deg<<<nBlkN, nThreads>>>(N);
    k_count<<<nBlkE, nThreads>>>(dst, E);
    k_scan1<<<nbScan, 1024>>>(N);
    k_scan2<<<1, 32>>>(nbScan);
    k_scan3<<<nBlkN, nThreads>>>(N, E);
    k_fill<<<nBlkE, nThreads>>>(src, dst, E);

    // --- Layer 1: x[N,25] @ W1[25,64] ---
    {
        int blocks = (N + 15) / 16;  // RPB = 256/(64/4) = 16
        k_gemm<25, 64, 0><<<blocks, 256>>>(x, W1, N);
        int aggBlocks = ((long)N * 32 + 255) / 256;
        k_agg<64><<<aggBlocks, 256>>>(b1, N);
    }
    // --- Layer 2: h[N,64] @ W2[64,64] ---
    {
        int blocks = (N + 15) / 16;
        k_gemm<64, 64, 1><<<blocks, 256>>>(nullptr, W2, N);
        int aggBlocks = ((long)N * 32 + 255) / 256;
        k_agg<64><<<aggBlocks, 256>>>(b2, N);
    }
    // --- Layer 3: h[N,64] @ W3[64,32] ---
    {
        int blocks = (N + 31) / 32;  // RPB = 256/(32/4) = 32
        k_gemm<64, 32, 1><<<blocks, 256>>>(nullptr, W3, N);
        int aggBlocks = ((long)N * 32 + 255) / 256;
        k_agg<32><<<aggBlocks, 256>>>(b3, N);
    }

    // --- Pool + MLP head ---
    k_pool_mlp<<<GMAX, 128>>>(batch, N, Wh1, bh1, Wh2, bh2, out);
}

// round 2
// speedup vs baseline: 1.0194x; 1.0194x over previous
#include <cuda_runtime.h>
#include <cuda_fp16.h>

// ---------------------------------------------------------------------------
// MutationAwareGNN: 3-layer GCN + mean pool + MLP head.
// R2: fp16 feature storage (fp32 accumulate), layer-1 aggregate-before-GEMM
// (GCN linearity: A_hat(XW) = (A_hat X)W), parallel block-sum scan, 4x edge
// unroll in aggregation. CSR pull-based, no float atomics.
// ---------------------------------------------------------------------------

#define NMAX 100000
#define EMAX 3200000
#define GMAX 256

__device__ int    g_deg[NMAX];
__device__ int    g_rowptr[NMAX + 1];
__device__ int    g_cursor[NMAX];
__device__ int    g_bsums[1024];
__device__ int    g_col[EMAX];
__device__ float  g_dinv[NMAX];
__device__ __half g_hA[NMAX * 64];
__device__ __half g_hB[NMAX * 64];

// ---------------------------- CSR construction ----------------------------

__global__ void k_zero_deg(int n) {
    int i = blockIdx.x * blockDim.x + threadIdx.x;
    if (i < n) g_deg[i] = 0;
}

__global__ void k_count(const int* __restrict__ dst, int E) {
    int e = blockIdx.x * blockDim.x + threadIdx.x;
    if (e < E) atomicAdd(&g_deg[dst[e]], 1);
}

__global__ void k_scan1(int n) {
    __shared__ int s[1024];
    int i = blockIdx.x * 1024 + threadIdx.x;
    int v = (i < n) ? g_deg[i] : 0;
    s[threadIdx.x] = v;
    __syncthreads();
    for (int off = 1; off < 1024; off <<= 1) {
        int t = (threadIdx.x >= (unsigned)off) ? s[threadIdx.x - off] : 0;
        __syncthreads();
        s[threadIdx.x] += t;
        __syncthreads();
    }
    if (i < n) g_rowptr[i] = s[threadIdx.x] - v;  // exclusive within chunk
    if (threadIdx.x == 1023) g_bsums[blockIdx.x] = s[1023];
}

// Parallel single-block scan of chunk sums (nb <= 1024).
__global__ void k_scan2(int nb) {
    __shared__ int s[1024];
    int v = (threadIdx.x < nb) ? g_bsums[threadIdx.x] : 0;
    s[threadIdx.x] = v;
    __syncthreads();
    for (int off = 1; off < 1024; off <<= 1) {
        int t = (threadIdx.x >= (unsigned)off) ? s[threadIdx.x - off] : 0;
        __syncthreads();
        s[threadIdx.x] += t;
        __syncthreads();
    }
    if (threadIdx.x < nb) g_bsums[threadIdx.x] = s[threadIdx.x] - v;  // exclusive
}

__global__ void k_scan3(int n, int E) {
    int i = blockIdx.x * blockDim.x + threadIdx.x;
    if (i < n) {
        int r = g_rowptr[i] + g_bsums[i >> 10];
        g_rowptr[i] = r;
        g_cursor[i] = r;
        g_dinv[i]   = rsqrtf((float)(g_deg[i] + 1));  // +1 self-loop
        if (i == 0) g_rowptr[n] = E;
    }
}

__global__ void k_fill(const int* __restrict__ src, const int* __restrict__ dst, int E) {
    int e = blockIdx.x * blockDim.x + threadIdx.x;
    if (e < E) {
        int d = dst[e];
        int p = atomicAdd(&g_cursor[d], 1);
        g_col[p] = src[e];
    }
}

// ------------------------------ Prep (layer 1) ------------------------------
// xs = dinv_j * x_j, 25 features padded to 32 fp16 -> g_hA (stride 32).

__global__ void k_prep(const float* __restrict__ x, int n) {
    int i = blockIdx.x * blockDim.x + threadIdx.x;
    if (i >= n * 32) return;
    int node = i >> 5, f = i & 31;
    float v = (f < 25) ? g_dinv[node] * __ldg(&x[node * 25 + f]) : 0.f;
    g_hA[i] = __float2half_rn(v);
}

// ----------------------------- Aggregation ---------------------------------
// Warp per node. SRC=0: g_hA -> g_hB ; SRC=1: g_hB -> g_hA.
// RELU=1: out = relu(dinv_i*acc + bias) ; RELU=0: out = dinv_i*acc.
// F=64: half2/lane (stride 64 halves). F=32: half/lane (stride 32 halves).

template <int F, int RELU, int SRC>
__global__ void k_agg_h(const float* __restrict__ bias, int n) {
    int gw   = (blockIdx.x * blockDim.x + threadIdx.x) >> 5;
    int lane = threadIdx.x & 31;
    if (gw >= n) return;
    int beg = g_rowptr[gw], end = g_rowptr[gw + 1];
    const __half* sb = SRC ? g_hB : g_hA;
    __half*       db = SRC ? g_hA : g_hB;
    float d = g_dinv[gw];

    if (F == 64) {
        const __half2* base = reinterpret_cast<const __half2*>(sb);
        float2 acc = __half22float2(base[gw * 32 + lane]);  // self-loop
        int e = beg;
        for (; e + 4 <= end; e += 4) {
            int j0 = __ldg(&g_col[e]);
            int j1 = __ldg(&g_col[e + 1]);
            int j2 = __ldg(&g_col[e + 2]);
            int j3 = __ldg(&g_col[e + 3]);
            float2 v0 = __half22float2(base[j0 * 32 + lane]);
            float2 v1 = __half22float2(base[j1 * 32 + lane]);
            float2 v2 = __half22float2(base[j2 * 32 + lane]);
            float2 v3 = __half22float2(base[j3 * 32 + lane]);
            acc.x += (v0.x + v1.x) + (v2.x + v3.x);
            acc.y += (v0.y + v1.y) + (v2.y + v3.y);
        }
        for (; e < end; e++) {
            float2 v = __half22float2(base[__ldg(&g_col[e]) * 32 + lane]);
            acc.x += v.x; acc.y += v.y;
        }
        float rx, ry;
        if (RELU) {
            rx = fmaxf(fmaf(acc.x, d, __ldg(&bias[lane * 2 + 0])), 0.f);
            ry = fmaxf(fmaf(acc.y, d, __ldg(&bias[lane * 2 + 1])), 0.f);
        } else {
            rx = acc.x * d; ry = acc.y * d;
        }
        reinterpret_cast<__half2*>(db)[gw * 32 + lane] = __floats2half2_rn(rx, ry);
    } else {  // F == 32
        float acc = __half2float(sb[gw * 32 + lane]);
        int e = beg;
        for (; e + 4 <= end; e += 4) {
            int j0 = __ldg(&g_col[e]);
            int j1 = __ldg(&g_col[e + 1]);
            int j2 = __ldg(&g_col[e + 2]);
            int j3 = __ldg(&g_col[e + 3]);
            float v0 = __half2float(sb[j0 * 32 + lane]);
            float v1 = __half2float(sb[j1 * 32 + lane]);
            float v2 = __half2float(sb[j2 * 32 + lane]);
            float v3 = __half2float(sb[j3 * 32 + lane]);
            acc += (v0 + v1) + (v2 + v3);
        }
        for (; e < end; e++)
            acc += __half2float(sb[__ldg(&g_col[e]) * 32 + lane]);
        float r = RELU ? fmaxf(fmaf(acc, d, __ldg(&bias[lane])), 0.f) : acc * d;
        db[gw * 32 + lane] = __float2half_rn(r);
    }
}

// ------------------------------- Dense GEMM --------------------------------
// fp16 in/out, fp32 accumulate, W fp32 in smem. EPI=0: scale by dinv (pre-agg),
// EPI=1: +bias, relu (layer-1 final). SRC=0: g_hA->g_hB ; SRC=1: g_hB->g_hA.

template <int FIN, int XSTR, int FOUT, int EPI, int SRC>
__global__ void k_gemm_h(const float* __restrict__ W, const float* __restrict__ bias, int n) {
    __shared__ float Wsh[FIN * FOUT];
    for (int i = threadIdx.x; i < FIN * FOUT; i += blockDim.x) Wsh[i] = W[i];
    __syncthreads();

    const __half* X = SRC ? g_hB : g_hA;
    __half*       O = SRC ? g_hA : g_hB;
    constexpr int TPR = FOUT / 4;
    constexpr int RPB = 256 / TPR;
    int row = blockIdx.x * RPB + (int)(threadIdx.x / TPR);
    if (row >= n) return;
    int fx = (threadIdx.x % TPR) * 4;

    const __half* xr = X + (long)row * XSTR;
    float4 acc = make_float4(0.f, 0.f, 0.f, 0.f);
#pragma unroll
    for (int k = 0; k < FIN; k++) {
        float xv = __half2float(__ldg(&xr[k]));
        float4 w = *reinterpret_cast<const float4*>(&Wsh[k * FOUT + fx]);
        acc.x = fmaf(xv, w.x, acc.x);
        acc.y = fmaf(xv, w.y, acc.y);
        acc.z = fmaf(xv, w.z, acc.z);
        acc.w = fmaf(xv, w.w, acc.w);
    }
    if (EPI == 0) {
        float d = g_dinv[row];
        acc.x *= d; acc.y *= d; acc.z *= d; acc.w *= d;
    } else {
        acc.x = fmaxf(acc.x + __ldg(&bias[fx + 0]), 0.f);
        acc.y = fmaxf(acc.y + __ldg(&bias[fx + 1]), 0.f);
        acc.z = fmaxf(acc.z + __ldg(&bias[fx + 2]), 0.f);
        acc.w = fmaxf(acc.w + __ldg(&bias[fx + 3]), 0.f);
    }
    __half2* op = reinterpret_cast<__half2*>(&O[(long)row * FOUT + fx]);
    op[0] = __floats2half2_rn(acc.x, acc.y);
    op[1] = __floats2half2_rn(acc.z, acc.w);
}

// ------------------------- Pool + MLP head (fused) --------------------------
// Final features fp16 in g_hA (stride 32). batch sorted -> binary search range.

__global__ void k_pool_mlp(const int* __restrict__ batch, int n,
                           const float* __restrict__ Wh1, const float* __restrict__ bh1,
                           const float* __restrict__ Wh2, const float* __restrict__ bh2,
                           float* __restrict__ out) {
    int g = blockIdx.x;
    int lo = 0, hi = n;
    while (lo < hi) { int mid = (lo + hi) >> 1; if (batch[mid] < g) lo = mid + 1; else hi = mid; }
    int start = lo;
    hi = n;
    while (lo < hi) { int mid = (lo + hi) >> 1; if (batch[mid] < g + 1) lo = mid + 1; else hi = mid; }
    int end = lo;

    __shared__ float partial[4][32];
    __shared__ float gsum[32];
    int f = threadIdx.x & 31;
    int r = threadIdx.x >> 5;
    float acc = 0.f;
    for (int i = start + r; i < end; i += 4) acc += __half2float(g_hA[(long)i * 32 + f]);
    partial[r][f] = acc;
    __syncthreads();

    if (threadIdx.x < 32) {
        float s = partial[0][f] + partial[1][f] + partial[2][f] + partial[3][f];
        float cnt = (float)((end - start) > 0 ? (end - start) : 1);
        gsum[f] = s / cnt;
    }
    __syncthreads();

    if (threadIdx.x < 32) {
        int o = threadIdx.x;
        float h = bh1[o];
#pragma unroll
        for (int k = 0; k < 32; k++) h = fmaf(gsum[k], Wh1[k * 32 + o], h);
        h = fmaxf(h, 0.f);
        float y = h * Wh2[o];
#pragma unroll
        for (int off = 16; off; off >>= 1) y += __shfl_down_sync(0xffffffffu, y, off);
        if (o == 0) out[g] = y + bh2[0];
    }
}

// ------------------------------- Launcher ----------------------------------

extern "C" void kernel_launch(void* const* d_in, const int* in_sizes, int n_in,
                              void* d_out, int out_size) {
    const float* x     = (const float*)d_in[0];
    const int*   ei    = (const int*)d_in[1];
    const int*   batch = (const int*)d_in[2];
    const float* W1  = (const float*)d_in[3];
    const float* b1  = (const float*)d_in[4];
    const float* W2  = (const float*)d_in[5];
    const float* b2  = (const float*)d_in[6];
    const float* W3  = (const float*)d_in[7];
    const float* b3  = (const float*)d_in[8];
    const float* Wh1 = (const float*)d_in[9];
    const float* bh1 = (const float*)d_in[10];
    const float* Wh2 = (const float*)d_in[11];
    const float* bh2 = (const float*)d_in[12];
    float* out = (float*)d_out;

    int N = in_sizes[0] / 25;
    int E = in_sizes[1] / 2;
    const int* src = ei;
    const int* dst = ei + E;

    int nThreads = 256;
    int nBlkN = (N + nThreads - 1) / nThreads;
    int nBlkE = (E + nThreads - 1) / nThreads;
    int nbScan = (N + 1023) / 1024;
    int aggBlocks = (N * 8 + 255) / 256 * 8 / 8;  // warp per node
    aggBlocks = (N + 7) / 8;

    // --- CSR build ---
    k_zero_deg<<<nBlkN, nThreads>>>(N);
    k_count<<<nBlkE, nThreads>>>(dst, E);
    k_scan1<<<nbScan, 1024>>>(N);
    k_scan2<<<1, 1024>>>(nbScan);
    k_scan3<<<nBlkN, nThreads>>>(N, E);
    k_fill<<<nBlkE, nThreads>>>(src, dst, E);

    // --- Layer 1: aggregate x first (linearity), then 25->64 GEMM ---
    k_prep<<<(N * 32 + 255) / 256, 256>>>(x, N);            // x -> g_hA (pad32)
    k_agg_h<32, 0, 0><<<aggBlocks, 256>>>(nullptr, N);      // g_hA -> g_hB
    k_gemm_h<25, 32, 64, 1, 1><<<(N + 15) / 16, 256>>>(W1, b1, N);  // g_hB -> g_hA

    // --- Layer 2: 64->64 GEMM (scale dinv), aggregate ---
    k_gemm_h<64, 64, 64, 0, 0><<<(N + 15) / 16, 256>>>(W2, nullptr, N);  // g_hA -> g_hB
    k_agg_h<64, 1, 1><<<aggBlocks, 256>>>(b2, N);                        // g_hB -> g_hA

    // --- Layer 3: 64->32 GEMM (scale dinv), aggregate ---
    k_gemm_h<64, 64, 32, 0, 0><<<(N + 31) / 32, 256>>>(W3, nullptr, N);  // g_hA -> g_hB
    k_agg_h<32, 1, 1><<<aggBlocks, 256>>>(b3, N);                        // g_hB -> g_hA

    // --- Pool + MLP head ---
    k_pool_mlp<<<GMAX, 128>>>(batch, N, Wh1, bh1, Wh2, bh2, out);
}

// round 3
// speedup vs baseline: 1.1728x; 1.1504x over previous
#include <cuda_runtime.h>
#include <cuda_fp16.h>

// ---------------------------------------------------------------------------
// MutationAwareGNN R3: multi-edge-per-warp gather aggregation (4-8 edges per
// warp load instruction, prefetched col indices), uint4-vectorized GEMM loads.
// fp16 storage / fp32 accumulate. CSR pull, no float atomics.
// ---------------------------------------------------------------------------

#define NMAX 100000
#define EMAX 3200000
#define GMAX 256

__device__ int    g_deg[NMAX];
__device__ int    g_rowptr[NMAX + 1];
__device__ int    g_cursor[NMAX];
__device__ int    g_bsums[1024];
__device__ int    g_col[EMAX];
__device__ float  g_dinv[NMAX];
__device__ __half g_hA[NMAX * 64];
__device__ __half g_hB[NMAX * 64];

// ---------------------------- CSR construction ----------------------------

__global__ void k_zero_deg(int n) {
    int i = blockIdx.x * blockDim.x + threadIdx.x;
    if (i < n) g_deg[i] = 0;
}

__global__ void k_count(const int* __restrict__ dst, int E) {
    int e = blockIdx.x * blockDim.x + threadIdx.x;
    if (e < E) atomicAdd(&g_deg[dst[e]], 1);
}

__global__ void k_scan1(int n) {
    __shared__ int s[1024];
    int i = blockIdx.x * 1024 + threadIdx.x;
    int v = (i < n) ? g_deg[i] : 0;
    s[threadIdx.x] = v;
    __syncthreads();
    for (int off = 1; off < 1024; off <<= 1) {
        int t = (threadIdx.x >= (unsigned)off) ? s[threadIdx.x - off] : 0;
        __syncthreads();
        s[threadIdx.x] += t;
        __syncthreads();
    }
    if (i < n) g_rowptr[i] = s[threadIdx.x] - v;
    if (threadIdx.x == 1023) g_bsums[blockIdx.x] = s[1023];
}

__global__ void k_scan2(int nb) {
    __shared__ int s[1024];
    int v = (threadIdx.x < nb) ? g_bsums[threadIdx.x] : 0;
    s[threadIdx.x] = v;
    __syncthreads();
    for (int off = 1; off < 1024; off <<= 1) {
        int t = (threadIdx.x >= (unsigned)off) ? s[threadIdx.x - off] : 0;
        __syncthreads();
        s[threadIdx.x] += t;
        __syncthreads();
    }
    if (threadIdx.x < nb) g_bsums[threadIdx.x] = s[threadIdx.x] - v;
}

__global__ void k_scan3(int n, int E) {
    int i = blockIdx.x * blockDim.x + threadIdx.x;
    if (i < n) {
        int r = g_rowptr[i] + g_bsums[i >> 10];
        g_rowptr[i] = r;
        g_cursor[i] = r;
        g_dinv[i]   = rsqrtf((float)(g_deg[i] + 1));
        if (i == 0) g_rowptr[n] = E;
    }
}

__global__ void k_fill(const int* __restrict__ src, const int* __restrict__ dst, int E) {
    int e = blockIdx.x * blockDim.x + threadIdx.x;
    if (e < E) {
        int d = dst[e];
        int p = atomicAdd(&g_cursor[d], 1);
        g_col[p] = src[e];
    }
}

// ------------------------------ Prep (layer 1) ------------------------------

__global__ void k_prep(const float* __restrict__ x, int n) {
    int i = blockIdx.x * blockDim.x + threadIdx.x;   // half2 slot
    if (i >= n * 16) return;
    int node = i >> 4, f2 = i & 15;
    float d = g_dinv[node];
    int f = f2 * 2;
    float a = (f     < 25) ? d * __ldg(&x[node * 25 + f])     : 0.f;
    float b = (f + 1 < 25) ? d * __ldg(&x[node * 25 + f + 1]) : 0.f;
    reinterpret_cast<__half2*>(g_hA)[i] = __floats2half2_rn(a, b);
}

// ----------------------------- Aggregation ---------------------------------
// Warp per node, multi-edge: LPR lanes cover one row via uint4 (16B = 8 fp16),
// 32/LPR edges in flight per warp load. Cross-group shfl_xor reduction.
// SRC=0: g_hA -> g_hB ; SRC=1: g_hB -> g_hA.

__device__ __forceinline__ void acc_u4(float* acc, uint4 v) {
    __half2 h0 = *reinterpret_cast<__half2*>(&v.x);
    __half2 h1 = *reinterpret_cast<__half2*>(&v.y);
    __half2 h2 = *reinterpret_cast<__half2*>(&v.z);
    __half2 h3 = *reinterpret_cast<__half2*>(&v.w);
    float2 f0 = __half22float2(h0), f1 = __half22float2(h1);
    float2 f2 = __half22float2(h2), f3 = __half22float2(h3);
    acc[0] += f0.x; acc[1] += f0.y; acc[2] += f1.x; acc[3] += f1.y;
    acc[4] += f2.x; acc[5] += f2.y; acc[6] += f3.x; acc[7] += f3.y;
}

template <int F, int RELU, int SRC>
__global__ void k_agg_v(const float* __restrict__ bias, int n) {
    constexpr int U4R = F / 8;        // uint4 per row: 8 (F=64) or 4 (F=32)
    constexpr int NG  = 32 / U4R;     // edge groups per warp: 4 or 8
    int gw   = (blockIdx.x * blockDim.x + threadIdx.x) >> 5;
    int lane = threadIdx.x & 31;
    if (gw >= n) return;
    int grp = lane / U4R;             // edge group
    int sub = lane % U4R;             // uint4 chunk within row
    int beg = g_rowptr[gw], end = g_rowptr[gw + 1];

    const uint4* base = reinterpret_cast<const uint4*>(SRC ? g_hB : g_hA);
    __half*      db   = SRC ? g_hA : g_hB;

    float acc[8] = {0.f, 0.f, 0.f, 0.f, 0.f, 0.f, 0.f, 0.f};
    if (grp == 0) acc_u4(acc, base[gw * U4R + sub]);   // self-loop term

    int e = beg + grp;
    int j = (e < end) ? __ldg(&g_col[e]) : 0;
    while (e < end) {
        int e2 = e + NG;
        int j2 = __ldg(&g_col[(e2 < end) ? e2 : e]);   // prefetch next col
        acc_u4(acc, base[j * U4R + sub]);
        e = e2;
        j = j2;
    }

    // reduce across edge groups
#pragma unroll
    for (int off = U4R; off < 32; off <<= 1) {
#pragma unroll
        for (int k = 0; k < 8; k++)
            acc[k] += __shfl_xor_sync(0xffffffffu, acc[k], off);
    }

    if (grp == 0) {
        float d = g_dinv[gw];
        __half out[8];
#pragma unroll
        for (int k = 0; k < 8; k++) {
            float r;
            if (RELU) r = fmaxf(fmaf(acc[k], d, __ldg(&bias[sub * 8 + k])), 0.f);
            else      r = acc[k] * d;
            out[k] = __float2half_rn(r);
        }
        reinterpret_cast<uint4*>(db)[gw * U4R + sub] = *reinterpret_cast<uint4*>(out);
    }
}

// ------------------------------- Dense GEMM --------------------------------
// fp16 in/out (uint4 row loads), fp32 accumulate, W fp32 in smem (padded).
// EPI=0: *dinv ; EPI=1: +bias, relu. SRC=0: g_hA->g_hB ; SRC=1: g_hB->g_hA.

template <int FINP, int FINW, int FOUT, int EPI, int SRC>
__global__ void k_gemm_h(const float* __restrict__ W, const float* __restrict__ bias, int n) {
    __shared__ float Wsh[FINP * FOUT];
    for (int i = threadIdx.x; i < FINP * FOUT; i += blockDim.x)
        Wsh[i] = (i < FINW * FOUT) ? W[i] : 0.f;
    __syncthreads();

    const __half* X = SRC ? g_hB : g_hA;
    __half*       O = SRC ? g_hA : g_hB;
    constexpr int TPR = FOUT / 4;
    constexpr int RPB = 256 / TPR;
    int row = blockIdx.x * RPB + (int)(threadIdx.x / TPR);
    if (row >= n) return;
    int fx = (threadIdx.x % TPR) * 4;

    const uint4* xr = reinterpret_cast<const uint4*>(X + (long)row * FINP);
    float4 acc = make_float4(0.f, 0.f, 0.f, 0.f);
#pragma unroll
    for (int q = 0; q < FINP / 8; q++) {
        uint4 v = __ldg(&xr[q]);
        __half2 hh[4];
        hh[0] = *reinterpret_cast<__half2*>(&v.x);
        hh[1] = *reinterpret_cast<__half2*>(&v.y);
        hh[2] = *reinterpret_cast<__half2*>(&v.z);
        hh[3] = *reinterpret_cast<__half2*>(&v.w);
#pragma unroll
        for (int t = 0; t < 4; t++) {
            float2 f = __half22float2(hh[t]);
            int k = q * 8 + t * 2;
            float4 w0 = *reinterpret_cast<const float4*>(&Wsh[k * FOUT + fx]);
            float4 w1 = *reinterpret_cast<const float4*>(&Wsh[(k + 1) * FOUT + fx]);
            acc.x = fmaf(f.x, w0.x, fmaf(f.y, w1.x, acc.x));
            acc.y = fmaf(f.x, w0.y, fmaf(f.y, w1.y, acc.y));
            acc.z = fmaf(f.x, w0.z, fmaf(f.y, w1.z, acc.z));
            acc.w = fmaf(f.x, w0.w, fmaf(f.y, w1.w, acc.w));
        }
    }
    if (EPI == 0) {
        float d = g_dinv[row];
        acc.x *= d; acc.y *= d; acc.z *= d; acc.w *= d;
    } else {
        acc.x = fmaxf(acc.x + __ldg(&bias[fx + 0]), 0.f);
        acc.y = fmaxf(acc.y + __ldg(&bias[fx + 1]), 0.f);
        acc.z = fmaxf(acc.z + __ldg(&bias[fx + 2]), 0.f);
        acc.w = fmaxf(acc.w + __ldg(&bias[fx + 3]), 0.f);
    }
    __half2* op = reinterpret_cast<__half2*>(&O[(long)row * FOUT + fx]);
    op[0] = __floats2half2_rn(acc.x, acc.y);
    op[1] = __floats2half2_rn(acc.z, acc.w);
}

// ------------------------- Pool + MLP head (fused) --------------------------

__global__ void k_pool_mlp(const int* __restrict__ batch, int n,
                           const float* __restrict__ Wh1, const float* __restrict__ bh1,
                           const float* __restrict__ Wh2, const float* __restrict__ bh2,
                           float* __restrict__ out) {
    int g = blockIdx.x;
    int lo = 0, hi = n;
    while (lo < hi) { int mid = (lo + hi) >> 1; if (batch[mid] < g) lo = mid + 1; else hi = mid; }
    int start = lo;
    hi = n;
    while (lo < hi) { int mid = (lo + hi) >> 1; if (batch[mid] < g + 1) lo = mid + 1; else hi = mid; }
    int end = lo;

    __shared__ float partial[4][32];
    __shared__ float gsum[32];
    int f = threadIdx.x & 31;
    int r = threadIdx.x >> 5;
    float acc = 0.f;
    for (int i = start + r; i < end; i += 4) acc += __half2float(g_hA[(long)i * 32 + f]);
    partial[r][f] = acc;
    __syncthreads();

    if (threadIdx.x < 32) {
        float s = partial[0][f] + partial[1][f] + partial[2][f] + partial[3][f];
        float cnt = (float)((end - start) > 0 ? (end - start) : 1);
        gsum[f] = s / cnt;
    }
    __syncthreads();

    if (threadIdx.x < 32) {
        int o = threadIdx.x;
        float h = bh1[o];
#pragma unroll
        for (int k = 0; k < 32; k++) h = fmaf(gsum[k], Wh1[k * 32 + o], h);
        h = fmaxf(h, 0.f);
        float y = h * Wh2[o];
#pragma unroll
        for (int off = 16; off; off >>= 1) y += __shfl_down_sync(0xffffffffu, y, off);
        if (o == 0) out[g] = y + bh2[0];
    }
}

// ------------------------------- Launcher ----------------------------------

extern "C" void kernel_launch(void* const* d_in, const int* in_sizes, int n_in,
                              void* d_out, int out_size) {
    const float* x     = (const float*)d_in[0];
    const int*   ei    = (const int*)d_in[1];
    const int*   batch = (const int*)d_in[2];
    const float* W1  = (const float*)d_in[3];
    const float* b1  = (const float*)d_in[4];
    const float* W2  = (const float*)d_in[5];
    const float* b2  = (const float*)d_in[6];
    const float* W3  = (const float*)d_in[7];
    const float* b3  = (const float*)d_in[8];
    const float* Wh1 = (const float*)d_in[9];
    const float* bh1 = (const float*)d_in[10];
    const float* Wh2 = (const float*)d_in[11];
    const float* bh2 = (const float*)d_in[12];
    float* out = (float*)d_out;

    int N = in_sizes[0] / 25;
    int E = in_sizes[1] / 2;
    const int* src = ei;
    const int* dst = ei + E;

    int nThreads = 256;
    int nBlkN = (N + nThreads - 1) / nThreads;
    int nBlkE = (E + nThreads - 1) / nThreads;
    int nbScan = (N + 1023) / 1024;
    int aggBlocks = (N + 7) / 8;   // warp per node, 8 warps/block

    // --- CSR build ---
    k_zero_deg<<<nBlkN, nThreads>>>(N);
    k_count<<<nBlkE, nThreads>>>(dst, E);
    k_scan1<<<nbScan, 1024>>>(N);
    k_scan2<<<1, 1024>>>(nbScan);
    k_scan3<<<nBlkN, nThreads>>>(N, E);
    k_fill<<<nBlkE, nThreads>>>(src, dst, E);

    // --- Layer 1: aggregate x first (linearity), then 25->64 GEMM ---
    k_prep<<<(N * 16 + 255) / 256, 256>>>(x, N);              // x -> g_hA (pad32)
    k_agg_v<32, 0, 0><<<aggBlocks, 256>>>(nullptr, N);        // g_hA -> g_hB
    k_gemm_h<32, 25, 64, 1, 1><<<(N + 15) / 16, 256>>>(W1, b1, N);  // g_hB -> g_hA

    // --- Layer 2 ---
    k_gemm_h<64, 64, 64, 0, 0><<<(N + 15) / 16, 256>>>(W2, nullptr, N);  // A -> B
    k_agg_v<64, 1, 1><<<aggBlocks, 256>>>(b2, N);                        // B -> A

    // --- Layer 3 ---
    k_gemm_h<64, 64, 32, 0, 0><<<(N + 31) / 32, 256>>>(W3, nullptr, N);  // A -> B
    k_agg_v<32, 1, 1><<<aggBlocks, 256>>>(b3, N);                        // B -> A

    // --- Pool + MLP head ---
    k_pool_mlp<<<GMAX, 128>>>(batch, N, Wh1, bh1, Wh2, bh2, out);
}

// round 4
// speedup vs baseline: 1.3692x; 1.1675x over previous
#include <cuda_runtime.h>
#include <cuda_fp16.h>

// ---------------------------------------------------------------------------
// MutationAwareGNN R4: agg with 2x-unrolled edge groups (2 gathers in flight
// per lane, cols prefetched 2 ahead); GEMM 2 rows/thread (halves LDS traffic,
// doubles FMA ILP); int4-vectorized CSR build. fp16 storage, fp32 accum.
// ---------------------------------------------------------------------------

#define NMAX 100000
#define EMAX 3200000
#define GMAX 256

__device__ int    g_deg[NMAX];
__device__ int    g_rowptr[NMAX + 1];
__device__ int    g_cursor[NMAX];
__device__ int    g_bsums[1024];
__device__ int    g_col[EMAX];
__device__ float  g_dinv[NMAX];
__device__ __half g_hA[NMAX * 64];
__device__ __half g_hB[NMAX * 64];

// ---------------------------- CSR construction ----------------------------

__global__ void k_zero_deg(int n) {
    int i = blockIdx.x * blockDim.x + threadIdx.x;
    if (i < n) g_deg[i] = 0;
}

__global__ void k_count(const int* __restrict__ dst, int E) {
    int e4 = (blockIdx.x * blockDim.x + threadIdx.x) * 4;
    if (e4 + 3 < E) {
        int4 d = *reinterpret_cast<const int4*>(&dst[e4]);
        atomicAdd(&g_deg[d.x], 1);
        atomicAdd(&g_deg[d.y], 1);
        atomicAdd(&g_deg[d.z], 1);
        atomicAdd(&g_deg[d.w], 1);
    } else {
        for (int e = e4; e < E; e++) atomicAdd(&g_deg[dst[e]], 1);
    }
}

__global__ void k_scan1(int n) {
    __shared__ int s[1024];
    int i = blockIdx.x * 1024 + threadIdx.x;
    int v = (i < n) ? g_deg[i] : 0;
    s[threadIdx.x] = v;
    __syncthreads();
    for (int off = 1; off < 1024; off <<= 1) {
        int t = (threadIdx.x >= (unsigned)off) ? s[threadIdx.x - off] : 0;
        __syncthreads();
        s[threadIdx.x] += t;
        __syncthreads();
    }
    if (i < n) g_rowptr[i] = s[threadIdx.x] - v;
    if (threadIdx.x == 1023) g_bsums[blockIdx.x] = s[1023];
}

__global__ void k_scan2(int nb) {
    __shared__ int s[1024];
    int v = (threadIdx.x < nb) ? g_bsums[threadIdx.x] : 0;
    s[threadIdx.x] = v;
    __syncthreads();
    for (int off = 1; off < 1024; off <<= 1) {
        int t = (threadIdx.x >= (unsigned)off) ? s[threadIdx.x - off] : 0;
        __syncthreads();
        s[threadIdx.x] += t;
        __syncthreads();
    }
    if (threadIdx.x < nb) g_bsums[threadIdx.x] = s[threadIdx.x] - v;
}

__global__ void k_scan3(int n, int E) {
    int i = blockIdx.x * blockDim.x + threadIdx.x;
    if (i < n) {
        int r = g_rowptr[i] + g_bsums[i >> 10];
        g_rowptr[i] = r;
        g_cursor[i] = r;
        g_dinv[i]   = rsqrtf((float)(g_deg[i] + 1));
        if (i == 0) g_rowptr[n] = E;
    }
}

__global__ void k_fill(const int* __restrict__ src, const int* __restrict__ dst, int E) {
    int e4 = (blockIdx.x * blockDim.x + threadIdx.x) * 4;
    if (e4 + 3 < E) {
        int4 s = *reinterpret_cast<const int4*>(&src[e4]);
        int4 d = *reinterpret_cast<const int4*>(&dst[e4]);
        g_col[atomicAdd(&g_cursor[d.x], 1)] = s.x;
        g_col[atomicAdd(&g_cursor[d.y], 1)] = s.y;
        g_col[atomicAdd(&g_cursor[d.z], 1)] = s.z;
        g_col[atomicAdd(&g_cursor[d.w], 1)] = s.w;
    } else {
        for (int e = e4; e < E; e++)
            g_col[atomicAdd(&g_cursor[dst[e]], 1)] = src[e];
    }
}

// ------------------------------ Prep (layer 1) ------------------------------

__global__ void k_prep(const float* __restrict__ x, int n) {
    int i = blockIdx.x * blockDim.x + threadIdx.x;   // half2 slot
    if (i >= n * 16) return;
    int node = i >> 4, f2 = i & 15;
    float d = g_dinv[node];
    int f = f2 * 2;
    float a = (f     < 25) ? d * __ldg(&x[node * 25 + f])     : 0.f;
    float b = (f + 1 < 25) ? d * __ldg(&x[node * 25 + f + 1]) : 0.f;
    reinterpret_cast<__half2*>(g_hA)[i] = __floats2half2_rn(a, b);
}

// ----------------------------- Aggregation ---------------------------------
// Warp per node. U4R lanes cover a row via uint4; NG=32/U4R edge groups.
// 2x unrolled: two independent gathers in flight per lane, cols prefetched
// two groups ahead. SRC=0: g_hA -> g_hB ; SRC=1: g_hB -> g_hA.

__device__ __forceinline__ void acc_u4(float* acc, uint4 v) {
    float2 f0 = __half22float2(*reinterpret_cast<__half2*>(&v.x));
    float2 f1 = __half22float2(*reinterpret_cast<__half2*>(&v.y));
    float2 f2 = __half22float2(*reinterpret_cast<__half2*>(&v.z));
    float2 f3 = __half22float2(*reinterpret_cast<__half2*>(&v.w));
    acc[0] += f0.x; acc[1] += f0.y; acc[2] += f1.x; acc[3] += f1.y;
    acc[4] += f2.x; acc[5] += f2.y; acc[6] += f3.x; acc[7] += f3.y;
}

template <int F, int RELU, int SRC>
__global__ void k_agg_v(const float* __restrict__ bias, int n) {
    constexpr int U4R = F / 8;        // uint4 per row: 8 (F=64) or 4 (F=32)
    constexpr int NG  = 32 / U4R;     // edge groups per warp: 4 or 8
    int gw   = (blockIdx.x * blockDim.x + threadIdx.x) >> 5;
    int lane = threadIdx.x & 31;
    if (gw >= n) return;
    int grp = lane / U4R;
    int sub = lane % U4R;
    int beg = g_rowptr[gw], end = g_rowptr[gw + 1];

    const uint4* base = reinterpret_cast<const uint4*>(SRC ? g_hB : g_hA);
    __half*      db   = SRC ? g_hA : g_hB;

    float acc[8] = {0.f, 0.f, 0.f, 0.f, 0.f, 0.f, 0.f, 0.f};
    if (grp == 0) acc_u4(acc, base[gw * U4R + sub]);   // self-loop

    int e  = beg + grp;
    int j0 = (e      < end) ? __ldg(&g_col[e])      : 0;
    int j1 = (e + NG < end) ? __ldg(&g_col[e + NG]) : 0;
    while (e + NG < end) {
        uint4 v0 = base[j0 * U4R + sub];
        uint4 v1 = base[j1 * U4R + sub];
        e += 2 * NG;
        j0 = (e      < end) ? __ldg(&g_col[e])      : 0;
        j1 = (e + NG < end) ? __ldg(&g_col[e + NG]) : 0;
        acc_u4(acc, v0);
        acc_u4(acc, v1);
    }
    if (e < end) acc_u4(acc, base[j0 * U4R + sub]);

#pragma unroll
    for (int off = U4R; off < 32; off <<= 1) {
#pragma unroll
        for (int k = 0; k < 8; k++)
            acc[k] += __shfl_xor_sync(0xffffffffu, acc[k], off);
    }

    if (grp == 0) {
        float d = g_dinv[gw];
        __half out[8];
#pragma unroll
        for (int k = 0; k < 8; k++) {
            float r;
            if (RELU) r = fmaxf(fmaf(acc[k], d, __ldg(&bias[sub * 8 + k])), 0.f);
            else      r = acc[k] * d;
            out[k] = __float2half_rn(r);
        }
        reinterpret_cast<uint4*>(db)[gw * U4R + sub] = *reinterpret_cast<uint4*>(out);
    }
}

// ------------------------------- Dense GEMM --------------------------------
// 2 rows per thread: shared W loads amortized over 2 accumulator chains.
// fp16 in/out (uint4 row loads), fp32 accumulate, W fp32 in smem (padded).

template <int FINP, int FINW, int FOUT, int EPI, int SRC>
__global__ void k_gemm_h(const float* __restrict__ W, const float* __restrict__ bias, int n) {
    __shared__ float Wsh[FINP * FOUT];
    for (int i = threadIdx.x; i < FINP * FOUT; i += blockDim.x)
        Wsh[i] = (i < FINW * FOUT) ? W[i] : 0.f;
    __syncthreads();

    const __half* X = SRC ? g_hB : g_hA;
    __half*       O = SRC ? g_hA : g_hB;
    constexpr int TPR  = FOUT / 4;       // threads per row
    constexpr int RPB  = 256 / TPR;      // row-slots per block
    constexpr int RPB2 = RPB * 2;        // rows per block (2 per thread)
    int slot = (int)(threadIdx.x / TPR);
    int row0 = blockIdx.x * RPB2 + slot;
    int row1 = row0 + RPB;
    int fx = (threadIdx.x % TPR) * 4;
    bool v0 = row0 < n, v1 = row1 < n;
    if (!v0) return;

    const uint4* xr0 = reinterpret_cast<const uint4*>(X + (long)row0 * FINP);
    const uint4* xr1 = reinterpret_cast<const uint4*>(X + (long)(v1 ? row1 : row0) * FINP);
    float4 a0 = make_float4(0.f, 0.f, 0.f, 0.f);
    float4 a1 = make_float4(0.f, 0.f, 0.f, 0.f);
#pragma unroll
    for (int q = 0; q < FINP / 8; q++) {
        uint4 p0 = __ldg(&xr0[q]);
        uint4 p1 = __ldg(&xr1[q]);
        const unsigned* u0 = &p0.x;
        const unsigned* u1 = &p1.x;
#pragma unroll
        for (int t = 0; t < 4; t++) {
            float2 f0 = __half22float2(*reinterpret_cast<const __half2*>(&u0[t]));
            float2 f1 = __half22float2(*reinterpret_cast<const __half2*>(&u1[t]));
            int k = q * 8 + t * 2;
            float4 w0 = *reinterpret_cast<const float4*>(&Wsh[k * FOUT + fx]);
            float4 w1 = *reinterpret_cast<const float4*>(&Wsh[(k + 1) * FOUT + fx]);
            a0.x = fmaf(f0.x, w0.x, fmaf(f0.y, w1.x, a0.x));
            a0.y = fmaf(f0.x, w0.y, fmaf(f0.y, w1.y, a0.y));
            a0.z = fmaf(f0.x, w0.z, fmaf(f0.y, w1.z, a0.z));
            a0.w = fmaf(f0.x, w0.w, fmaf(f0.y, w1.w, a0.w));
            a1.x = fmaf(f1.x, w0.x, fmaf(f1.y, w1.x, a1.x));
            a1.y = fmaf(f1.x, w0.y, fmaf(f1.y, w1.y, a1.y));
            a1.z = fmaf(f1.x, w0.z, fmaf(f1.y, w1.z, a1.z));
            a1.w = fmaf(f1.x, w0.w, fmaf(f1.y, w1.w, a1.w));
        }
    }

    float bx = 0.f, by = 0.f, bz = 0.f, bw = 0.f;
    if (EPI == 1) {
        bx = __ldg(&bias[fx + 0]); by = __ldg(&bias[fx + 1]);
        bz = __ldg(&bias[fx + 2]); bw = __ldg(&bias[fx + 3]);
    }
    {
        float4 acc = a0;
        if (EPI == 0) {
            float d = g_dinv[row0];
            acc.x *= d; acc.y *= d; acc.z *= d; acc.w *= d;
        } else {
            acc.x = fmaxf(acc.x + bx, 0.f); acc.y = fmaxf(acc.y + by, 0.f);
            acc.z = fmaxf(acc.z + bz, 0.f); acc.w = fmaxf(acc.w + bw, 0.f);
        }
        __half2* op = reinterpret_cast<__half2*>(&O[(long)row0 * FOUT + fx]);
        op[0] = __floats2half2_rn(acc.x, acc.y);
        op[1] = __floats2half2_rn(acc.z, acc.w);
    }
    if (v1) {
        float4 acc = a1;
        if (EPI == 0) {
            float d = g_dinv[row1];
            acc.x *= d; acc.y *= d; acc.z *= d; acc.w *= d;
        } else {
            acc.x = fmaxf(acc.x + bx, 0.f); acc.y = fmaxf(acc.y + by, 0.f);
            acc.z = fmaxf(acc.z + bz, 0.f); acc.w = fmaxf(acc.w + bw, 0.f);
        }
        __half2* op = reinterpret_cast<__half2*>(&O[(long)row1 * FOUT + fx]);
        op[0] = __floats2half2_rn(acc.x, acc.y);
        op[1] = __floats2half2_rn(acc.z, acc.w);
    }
}

// ------------------------- Pool + MLP head (fused) --------------------------

__global__ void k_pool_mlp(const int* __restrict__ batch, int n,
                           const float* __restrict__ Wh1, const float* __restrict__ bh1,
                           const float* __restrict__ Wh2, const float* __restrict__ bh2,
                           float* __restrict__ out) {
    int g = blockIdx.x;
    int lo = 0, hi = n;
    while (lo < hi) { int mid = (lo + hi) >> 1; if (batch[mid] < g) lo = mid + 1; else hi = mid; }
    int start = lo;
    hi = n;
    while (lo < hi) { int mid = (lo + hi) >> 1; if (batch[mid] < g + 1) lo = mid + 1; else hi = mid; }
    int end = lo;

    __shared__ float partial[4][32];
    __shared__ float gsum[32];
    int f = threadIdx.x & 31;
    int r = threadIdx.x >> 5;
    float acc = 0.f;
    for (int i = start + r; i < end; i += 4) acc += __half2float(g_hA[(long)i * 32 + f]);
    partial[r][f] = acc;
    __syncthreads();

    if (threadIdx.x < 32) {
        float s = partial[0][f] + partial[1][f] + partial[2][f] + partial[3][f];
        float cnt = (float)((end - start) > 0 ? (end - start) : 1);
        gsum[f] = s / cnt;
    }
    __syncthreads();

    if (threadIdx.x < 32) {
        int o = threadIdx.x;
        float h = bh1[o];
#pragma unroll
        for (int k = 0; k < 32; k++) h = fmaf(gsum[k], Wh1[k * 32 + o], h);
        h = fmaxf(h, 0.f);
        float y = h * Wh2[o];
#pragma unroll
        for (int off = 16; off; off >>= 1) y += __shfl_down_sync(0xffffffffu, y, off);
        if (o == 0) out[g] = y + bh2[0];
    }
}

// ------------------------------- Launcher ----------------------------------

extern "C" void kernel_launch(void* const* d_in, const int* in_sizes, int n_in,
                              void* d_out, int out_size) {
    const float* x     = (const float*)d_in[0];
    const int*   ei    = (const int*)d_in[1];
    const int*   batch = (const int*)d_in[2];
    const float* W1  = (const float*)d_in[3];
    const float* b1  = (const float*)d_in[4];
    const float* W2  = (const float*)d_in[5];
    const float* b2  = (const float*)d_in[6];
    const float* W3  = (const float*)d_in[7];
    const float* b3  = (const float*)d_in[8];
    const float* Wh1 = (const float*)d_in[9];
    const float* bh1 = (const float*)d_in[10];
    const float* Wh2 = (const float*)d_in[11];
    const float* bh2 = (const float*)d_in[12];
    float* out = (float*)d_out;

    int N = in_sizes[0] / 25;
    int E = in_sizes[1] / 2;
    const int* src = ei;
    const int* dst = ei + E;

    int nThreads = 256;
    int nBlkN = (N + nThreads - 1) / nThreads;
    int nBlkE4 = (E + nThreads * 4 - 1) / (nThreads * 4);
    int nbScan = (N + 1023) / 1024;
    int aggBlocks = (N + 7) / 8;

    // --- CSR build ---
    k_zero_deg<<<nBlkN, nThreads>>>(N);
    k_count<<<nBlkE4, nThreads>>>(dst, E);
    k_scan1<<<nbScan, 1024>>>(N);
    k_scan2<<<1, 1024>>>(nbScan);
    k_scan3<<<nBlkN, nThreads>>>(N, E);
    k_fill<<<nBlkE4, nThreads>>>(src, dst, E);

    // --- Layer 1: aggregate x first (linearity), then 25->64 GEMM ---
    k_prep<<<(N * 16 + 255) / 256, 256>>>(x, N);              // x -> A
    k_agg_v<32, 0, 0><<<aggBlocks, 256>>>(nullptr, N);        // A -> B
    k_gemm_h<32, 25, 64, 1, 1><<<(N + 31) / 32, 256>>>(W1, b1, N);  // B -> A

    // --- Layer 2 ---
    k_gemm_h<64, 64, 64, 0, 0><<<(N + 31) / 32, 256>>>(W2, nullptr, N);  // A -> B
    k_agg_v<64, 1, 1><<<aggBlocks, 256>>>(b2, N);                        // B -> A

    // --- Layer 3 ---
    k_gemm_h<64, 64, 32, 0, 0><<<(N + 63) / 64, 256>>>(W3, nullptr, N);  // A -> B
    k_agg_v<32, 1, 1><<<aggBlocks, 256>>>(b3, N);                        // B -> A

    // --- Pool + MLP head ---
    k_pool_mlp<<<GMAX, 128>>>(batch, N, Wh1, bh1, Wh2, bh2, out);
}